// round 2
// baseline (speedup 1.0000x reference)
#include <cuda_runtime.h>
#include <math.h>

// Problem dimensions (fixed by the reference)
#define B_SZ 16
#define S_SZ 512
#define W_SZ 5
#define D_SZ 200
#define H_SZ 768
#define M1 (B_SZ * S_SZ * W_SZ)   // 40960 rows for word-transform GEMMs
#define MQ (B_SZ * S_SZ)          // 8192 tokens
#define NMASK (MQ * W_SZ)         // 40960 mask entries

// Scratch (alloc-free rule: __device__ globals)
__device__ float g_tmp[M1 * H_SZ];   // tanh(WE @ W1 + b1)
__device__ float g_we [M1 * H_SZ];   // word_transform output
__device__ float g_q  [MQ * H_SZ];   // layer_output @ attn_W
__device__ float g_maskf[NMASK];     // normalized mask as float
__device__ int   g_mask_is32;        // 1 if mask buffer is int32

// ---------------------------------------------------------------------------
// Mask dtype detection: interpret first NMASK/2 entries as int64. If the data
// is genuinely int64 (values 0/1), every such value is 0 or 1. If the data is
// int32, packed pairs (lo,hi) give values >= 2^32 whenever hi!=0 (half the
// entries) -> flag. Reads are bounded to NMASK*4 bytes = the int32 buffer
// size, so no OOB under either interpretation.
// ---------------------------------------------------------------------------
__global__ void detect_mask_kernel(const long long* __restrict__ m64)
{
    int i = blockIdx.x * blockDim.x + threadIdx.x;
    if (i < NMASK / 2) {
        unsigned long long v = (unsigned long long)m64[i];
        if (v > 1ULL) atomicOr(&g_mask_is32, 1);
    }
}

__global__ void normalize_mask_kernel(const void* __restrict__ mraw)
{
    int i = blockIdx.x * blockDim.x + threadIdx.x;
    if (i >= NMASK) return;
    float v;
    if (g_mask_is32) {
        v = (float)((const int*)mraw)[i];
    } else {
        v = (float)((const long long*)mraw)[i];
    }
    g_maskf[i] = v;
}

// ---------------------------------------------------------------------------
// FP32 SGEMM: C[M,N] = op(A[M,K] @ B[K,N] + bias)
// Tile 128x64, BK=16, 256 threads, 8x4 per-thread microtile.
// ---------------------------------------------------------------------------
template <bool TANH, bool BIAS>
__global__ __launch_bounds__(256)
void sgemm128x64(const float* __restrict__ A,
                 const float* __restrict__ Bm,
                 const float* __restrict__ bias,
                 float* __restrict__ C,
                 int M, int N, int K)
{
    const int BM = 128, BN = 64, BK = 16;
    __shared__ float As[BM][BK];      // [m][k]
    __shared__ float Bs[BK][BN];      // [k][n]

    const int tid = threadIdx.x;          // 0..255
    const int tx  = tid & 15;             // n-direction (16 threads * 4 cols)
    const int ty  = tid >> 4;             // m-direction (16 threads * 8 rows)
    const int m0  = blockIdx.y * BM;
    const int n0  = blockIdx.x * BN;

    float acc[8][4];
    #pragma unroll
    for (int i = 0; i < 8; i++)
        #pragma unroll
        for (int j = 0; j < 4; j++)
            acc[i][j] = 0.f;

    for (int k0 = 0; k0 < K; k0 += BK) {
        #pragma unroll
        for (int i = 0; i < 8; i++) {
            int idx = tid + i * 256;
            int r = idx >> 4;
            int c = idx & 15;
            int gk = k0 + c;
            As[r][c] = (gk < K) ? A[(size_t)(m0 + r) * K + gk] : 0.f;
        }
        #pragma unroll
        for (int i = 0; i < 4; i++) {
            int idx = tid + i * 256;
            int r = idx >> 6;
            int c = idx & 63;
            int gk = k0 + r;
            Bs[r][c] = (gk < K) ? Bm[(size_t)gk * N + n0 + c] : 0.f;
        }
        __syncthreads();

        #pragma unroll
        for (int k = 0; k < BK; k++) {
            float a[8];
            #pragma unroll
            for (int i = 0; i < 8; i++)
                a[i] = As[ty * 8 + i][k];
            float4 bv = *reinterpret_cast<const float4*>(&Bs[k][tx * 4]);
            float b0 = bv.x, b1 = bv.y, b2 = bv.z, b3 = bv.w;
            #pragma unroll
            for (int i = 0; i < 8; i++) {
                acc[i][0] = fmaf(a[i], b0, acc[i][0]);
                acc[i][1] = fmaf(a[i], b1, acc[i][1]);
                acc[i][2] = fmaf(a[i], b2, acc[i][2]);
                acc[i][3] = fmaf(a[i], b3, acc[i][3]);
            }
        }
        __syncthreads();
    }

    float bias_v[4] = {0.f, 0.f, 0.f, 0.f};
    if (BIAS) {
        #pragma unroll
        for (int j = 0; j < 4; j++)
            bias_v[j] = bias[n0 + tx * 4 + j];
    }
    #pragma unroll
    for (int i = 0; i < 8; i++) {
        int m = m0 + ty * 8 + i;
        float4 v;
        float r0 = acc[i][0] + bias_v[0];
        float r1 = acc[i][1] + bias_v[1];
        float r2 = acc[i][2] + bias_v[2];
        float r3 = acc[i][3] + bias_v[3];
        if (TANH) { r0 = tanhf(r0); r1 = tanhf(r1); r2 = tanhf(r2); r3 = tanhf(r3); }
        v.x = r0; v.y = r1; v.z = r2; v.w = r3;
        *reinterpret_cast<float4*>(&C[(size_t)m * N + n0 + tx * 4]) = v;
    }
}

// ---------------------------------------------------------------------------
// Fused epilogue: per token (b,s):
//   scores_w = <q, we_w>; masked softmax over W=5;
//   agg = sum_w alpha_w * we_w; h = layer_output + agg; LayerNorm(h).
// One block of 256 threads per token; each thread owns 3 H-elements.
// ---------------------------------------------------------------------------
__global__ __launch_bounds__(256)
void epilogue_kernel(const float* __restrict__ lo,
                     const float* __restrict__ gamma,
                     const float* __restrict__ beta,
                     float* __restrict__ out)
{
    const int bs  = blockIdx.x;       // 0..8191
    const int tid = threadIdx.x;      // 0..255

    __shared__ float red[5][256];
    __shared__ float s_alpha[5];

    const float* qrow  = g_q  + (size_t)bs * H_SZ;
    const float* werow = g_we + (size_t)bs * W_SZ * H_SZ;
    const float* lorow = lo   + (size_t)bs * H_SZ;

    float qv[3], lov[3], wev[5][3];
    #pragma unroll
    for (int e = 0; e < 3; e++) {
        int h = tid + e * 256;
        qv[e]  = qrow[h];
        lov[e] = lorow[h];
        #pragma unroll
        for (int w = 0; w < W_SZ; w++)
            wev[w][e] = werow[w * H_SZ + h];
    }

    #pragma unroll
    for (int w = 0; w < W_SZ; w++) {
        float d = 0.f;
        #pragma unroll
        for (int e = 0; e < 3; e++)
            d = fmaf(qv[e], wev[w][e], d);
        red[w][tid] = d;
    }
    __syncthreads();
    for (int s = 128; s > 0; s >>= 1) {
        if (tid < s) {
            #pragma unroll
            for (int w = 0; w < W_SZ; w++)
                red[w][tid] += red[w][tid + s];
        }
        __syncthreads();
    }

    if (tid == 0) {
        float sc[5];
        float mx = -1e30f;
        #pragma unroll
        for (int w = 0; w < W_SZ; w++) {
            float mk = g_maskf[(size_t)bs * W_SZ + w];
            sc[w] = red[w][0] + (1.f - mk) * (-10000.f);
            mx = fmaxf(mx, sc[w]);
        }
        float sum = 0.f;
        #pragma unroll
        for (int w = 0; w < W_SZ; w++) {
            sc[w] = expf(sc[w] - mx);
            sum += sc[w];
        }
        float inv = 1.f / sum;
        #pragma unroll
        for (int w = 0; w < W_SZ; w++)
            s_alpha[w] = sc[w] * inv;
    }
    __syncthreads();

    float alpha[5];
    #pragma unroll
    for (int w = 0; w < W_SZ; w++) alpha[w] = s_alpha[w];

    float hv[3];
    float psum = 0.f, psq = 0.f;
    #pragma unroll
    for (int e = 0; e < 3; e++) {
        float agg = 0.f;
        #pragma unroll
        for (int w = 0; w < W_SZ; w++)
            agg = fmaf(alpha[w], wev[w][e], agg);
        hv[e] = lov[e] + agg;
        psum += hv[e];
        psq  = fmaf(hv[e], hv[e], psq);
    }
    __syncthreads();   // red[] reuse
    red[0][tid] = psum;
    red[1][tid] = psq;
    __syncthreads();
    for (int s = 128; s > 0; s >>= 1) {
        if (tid < s) {
            red[0][tid] += red[0][tid + s];
            red[1][tid] += red[1][tid + s];
        }
        __syncthreads();
    }

    const float inv_h = 1.f / (float)H_SZ;
    float mu   = red[0][0] * inv_h;
    float var  = red[1][0] * inv_h - mu * mu;
    float rstd = rsqrtf(var + 1e-12f);

    #pragma unroll
    for (int e = 0; e < 3; e++) {
        int h = tid + e * 256;
        out[(size_t)bs * H_SZ + h] = (hv[e] - mu) * rstd * gamma[h] + beta[h];
    }
}

// ---------------------------------------------------------------------------
// Launch
// ---------------------------------------------------------------------------
extern "C" void kernel_launch(void* const* d_in, const int* in_sizes, int n_in,
                              void* d_out, int out_size)
{
    const float* lo     = (const float*)d_in[0];  // [B,S,H]
    const float* we_in  = (const float*)d_in[1];  // [B,S,W,D]
    const void*  mask   = d_in[2];                // [B,S,W] int32 or int64
    const float* W1     = (const float*)d_in[3];  // [D,H]
    const float* b1     = (const float*)d_in[4];  // [H]
    const float* W2     = (const float*)d_in[5];  // [H,H]
    const float* b2     = (const float*)d_in[6];  // [H]
    const float* attn_W = (const float*)d_in[7];  // [H,H]
    const float* gamma  = (const float*)d_in[8];  // [H]
    const float* beta   = (const float*)d_in[9];  // [H]
    float*       out    = (float*)d_out;

    float *tmp_p, *we_p, *q_p;
    cudaGetSymbolAddress((void**)&tmp_p, g_tmp);
    cudaGetSymbolAddress((void**)&we_p,  g_we);
    cudaGetSymbolAddress((void**)&q_p,   g_q);

    // Mask dtype detection + normalization (graph-capturable: memsetAsync + kernels)
    int* flag_p;
    cudaGetSymbolAddress((void**)&flag_p, g_mask_is32);
    cudaMemsetAsync(flag_p, 0, sizeof(int));
    detect_mask_kernel<<<(NMASK / 2 + 255) / 256, 256>>>((const long long*)mask);
    normalize_mask_kernel<<<(NMASK + 255) / 256, 256>>>(mask);

    dim3 blk(256);
    dim3 grid1(H_SZ / 64, M1 / 128);   // (12, 320)
    dim3 grid3(H_SZ / 64, MQ / 128);   // (12, 64)

    // GEMM1: tmp = tanh(WE @ W1 + b1)   [40960 x 768], K=200
    sgemm128x64<true,  true ><<<grid1, blk>>>(we_in, W1, b1, tmp_p, M1, H_SZ, D_SZ);
    // GEMM2: we = tmp @ W2 + b2         [40960 x 768], K=768
    sgemm128x64<false, true ><<<grid1, blk>>>(tmp_p, W2, b2, we_p, M1, H_SZ, H_SZ);
    // GEMM3: q = layer_output @ attn_W  [8192 x 768], K=768
    sgemm128x64<false, false><<<grid3, blk>>>(lo, attn_W, nullptr, q_p, MQ, H_SZ, H_SZ);
    // Fused attention + residual + LayerNorm
    epilogue_kernel<<<MQ, 256>>>(lo, gamma, beta, out);
}

// round 3
// speedup vs baseline: 2.4354x; 2.4354x over previous
#include <cuda_runtime.h>
#include <math.h>
#include <stdint.h>

// Problem dimensions (fixed by the reference)
#define B_SZ 16
#define S_SZ 512
#define W_SZ 5
#define D_SZ 200
#define H_SZ 768
#define M1 (B_SZ * S_SZ * W_SZ)   // 40960 rows for word-transform GEMMs
#define MQ (B_SZ * S_SZ)          // 8192 tokens
#define NMASK (MQ * W_SZ)         // 40960 mask entries

// Scratch (alloc-free rule: __device__ globals)
__device__ float g_tmp[M1 * H_SZ];   // tanh(WE @ W1 + b1)
__device__ float g_we [M1 * H_SZ];   // word_transform output
__device__ float g_q  [MQ * H_SZ];   // layer_output @ attn_W
__device__ float g_maskf[NMASK];     // normalized mask as float
__device__ int   g_mask_is32;        // 1 if mask buffer is int32

// ---------------------------------------------------------------------------
// Mask dtype detection (same as passing R2 version)
// ---------------------------------------------------------------------------
__global__ void detect_mask_kernel(const long long* __restrict__ m64)
{
    int i = blockIdx.x * blockDim.x + threadIdx.x;
    if (i < NMASK / 2) {
        unsigned long long v = (unsigned long long)m64[i];
        if (v > 1ULL) atomicOr(&g_mask_is32, 1);
    }
}

__global__ void normalize_mask_kernel(const void* __restrict__ mraw)
{
    int i = blockIdx.x * blockDim.x + threadIdx.x;
    if (i >= NMASK) return;
    float v;
    if (g_mask_is32) v = (float)((const int*)mraw)[i];
    else             v = (float)((const long long*)mraw)[i];
    g_maskf[i] = v;
}

// ---------------------------------------------------------------------------
// TF32 tensor-core GEMM: C[M,N] = op(A[M,K] @ B[K,N] + bias)
// BM=128, BN=128, BK=32, 256 threads = 8 warps (2x4), warp tile 64x32.
// mma.sync.aligned.m16n8k8.row.col.f32.tf32.tf32.f32
// cp.async double-buffered SMEM; A pad->stride 36, B pad->stride 136
// (both verified conflict-free for the fragment access patterns).
// M % 128 == 0, N % 128 == 0; K ragged (zero-filled, K % 4 == 0).
// ---------------------------------------------------------------------------
#define AS_STRIDE 36
#define BS_STRIDE 136
#define AS_ELEMS (128 * AS_STRIDE)
#define BS_ELEMS (32 * BS_STRIDE)
#define SMEM_BYTES ((2 * AS_ELEMS + 2 * BS_ELEMS) * 4)

__device__ __forceinline__ void cp_async16(uint32_t dst, const void* src, int ssize)
{
    asm volatile("cp.async.cg.shared.global [%0], [%1], 16, %2;\n"
                 :: "r"(dst), "l"(src), "r"(ssize));
}
__device__ __forceinline__ void cp_commit() { asm volatile("cp.async.commit_group;\n"); }
__device__ __forceinline__ void cp_wait0()  { asm volatile("cp.async.wait_group 0;\n"); }

__device__ __forceinline__ uint32_t f2tf32(float f)
{
    uint32_t u;
    asm("cvt.rna.tf32.f32 %0, %1;\n" : "=r"(u) : "f"(f));
    return u;
}

template <bool TANH, bool BIAS>
__global__ __launch_bounds__(256)
void tf32_gemm(const float* __restrict__ A,
               const float* __restrict__ Bm,
               const float* __restrict__ bias,
               float* __restrict__ C,
               int M, int N, int K)
{
    extern __shared__ float smem[];
    float* As[2] = { smem,                smem + AS_ELEMS };
    float* Bs[2] = { smem + 2 * AS_ELEMS, smem + 2 * AS_ELEMS + BS_ELEMS };

    const int tid  = threadIdx.x;
    const int lane = tid & 31;
    const int wid  = tid >> 5;
    const int wm   = (wid & 1) * 64;   // warp row base within block tile
    const int wn   = (wid >> 1) * 32;  // warp col base within block tile
    const int g    = lane >> 2;        // groupID 0..7
    const int tg   = lane & 3;         // thread-in-group 0..3
    const int m0   = blockIdx.y * 128;
    const int n0   = blockIdx.x * 128;

    // Per-thread cp.async coordinates
    // A tile: 128 rows x 32 cols -> 1024 float4; 4 per thread
    const int ar[4] = { (tid + 0*256) >> 3, (tid + 1*256) >> 3, (tid + 2*256) >> 3, (tid + 3*256) >> 3 };
    const int ac    = (tid & 7) * 4;  // col within tile, same for all 4 (idx&7 invariant under +256)
    // B tile: 32 rows x 128 cols -> 1024 float4; 4 per thread
    const int br[4] = { (tid + 0*256) >> 5, (tid + 1*256) >> 5, (tid + 2*256) >> 5, (tid + 3*256) >> 5 };
    const int bc    = (tid & 31) * 4;

    uint32_t as_base[2], bs_base[2];
    as_base[0] = (uint32_t)__cvta_generic_to_shared(As[0]);
    as_base[1] = (uint32_t)__cvta_generic_to_shared(As[1]);
    bs_base[0] = (uint32_t)__cvta_generic_to_shared(Bs[0]);
    bs_base[1] = (uint32_t)__cvta_generic_to_shared(Bs[1]);

    float acc[4][4][4];
    #pragma unroll
    for (int mi = 0; mi < 4; mi++)
        #pragma unroll
        for (int ni = 0; ni < 4; ni++)
            #pragma unroll
            for (int r = 0; r < 4; r++)
                acc[mi][ni][r] = 0.f;

    const int tiles = (K + 31) / 32;

    // -------- tile loader --------
    auto load_tile = [&](int buf, int k0) {
        #pragma unroll
        for (int i = 0; i < 4; i++) {
            int gk = k0 + ac;
            int ok = (gk < K) ? 16 : 0;
            int gks = ok ? gk : 0;
            cp_async16(as_base[buf] + (ar[i] * AS_STRIDE + ac) * 4,
                       A + (size_t)(m0 + ar[i]) * K + gks, ok);
        }
        #pragma unroll
        for (int i = 0; i < 4; i++) {
            int gk = k0 + br[i];
            int ok = (gk < K) ? 16 : 0;
            int gks = ok ? gk : 0;
            cp_async16(bs_base[buf] + (br[i] * BS_STRIDE + bc) * 4,
                       Bm + (size_t)gks * N + n0 + bc, ok);
        }
        cp_commit();
    };

    load_tile(0, 0);

    int buf = 0;
    for (int t = 0; t < tiles; t++) {
        cp_wait0();
        __syncthreads();
        if (t + 1 < tiles)
            load_tile(buf ^ 1, (t + 1) * 32);

        const float* Ab = As[buf];
        const float* Bb = Bs[buf];

        #pragma unroll
        for (int s = 0; s < 4; s++) {
            const int kb = s * 8;
            // A fragments: 4 m-frags x 4 regs
            uint32_t af[4][4];
            #pragma unroll
            for (int mi = 0; mi < 4; mi++) {
                const float* p = Ab + (wm + mi * 16 + g) * AS_STRIDE + kb + tg;
                af[mi][0] = f2tf32(p[0]);
                af[mi][1] = f2tf32(p[8 * AS_STRIDE]);
                af[mi][2] = f2tf32(p[4]);
                af[mi][3] = f2tf32(p[8 * AS_STRIDE + 4]);
            }
            // B fragments: 4 n-frags x 2 regs
            uint32_t bf[4][2];
            #pragma unroll
            for (int ni = 0; ni < 4; ni++) {
                const float* p = Bb + (kb + tg) * BS_STRIDE + wn + ni * 8 + g;
                bf[ni][0] = f2tf32(p[0]);
                bf[ni][1] = f2tf32(p[4 * BS_STRIDE]);
            }
            #pragma unroll
            for (int mi = 0; mi < 4; mi++)
                #pragma unroll
                for (int ni = 0; ni < 4; ni++) {
                    asm volatile(
                        "mma.sync.aligned.m16n8k8.row.col.f32.tf32.tf32.f32 "
                        "{%0,%1,%2,%3}, {%4,%5,%6,%7}, {%8,%9}, {%0,%1,%2,%3};\n"
                        : "+f"(acc[mi][ni][0]), "+f"(acc[mi][ni][1]),
                          "+f"(acc[mi][ni][2]), "+f"(acc[mi][ni][3])
                        : "r"(af[mi][0]), "r"(af[mi][1]), "r"(af[mi][2]), "r"(af[mi][3]),
                          "r"(bf[ni][0]), "r"(bf[ni][1]));
                }
        }
        __syncthreads();
        buf ^= 1;
    }

    // -------- epilogue --------
    #pragma unroll
    for (int ni = 0; ni < 4; ni++) {
        const int col = n0 + wn + ni * 8 + tg * 2;
        float b0 = 0.f, b1 = 0.f;
        if (BIAS) { b0 = bias[col]; b1 = bias[col + 1]; }
        #pragma unroll
        for (int mi = 0; mi < 4; mi++) {
            const int row = m0 + wm + mi * 16 + g;
            float r0 = acc[mi][ni][0] + b0;
            float r1 = acc[mi][ni][1] + b1;
            float r2 = acc[mi][ni][2] + b0;
            float r3 = acc[mi][ni][3] + b1;
            if (TANH) { r0 = tanhf(r0); r1 = tanhf(r1); r2 = tanhf(r2); r3 = tanhf(r3); }
            float2 v0 = make_float2(r0, r1);
            float2 v1 = make_float2(r2, r3);
            *reinterpret_cast<float2*>(&C[(size_t)row * N + col])       = v0;
            *reinterpret_cast<float2*>(&C[(size_t)(row + 8) * N + col]) = v1;
        }
    }
}

// ---------------------------------------------------------------------------
// Fused epilogue (unchanged from passing R2 version)
// ---------------------------------------------------------------------------
__global__ __launch_bounds__(256)
void epilogue_kernel(const float* __restrict__ lo,
                     const float* __restrict__ gamma,
                     const float* __restrict__ beta,
                     float* __restrict__ out)
{
    const int bs  = blockIdx.x;
    const int tid = threadIdx.x;

    __shared__ float red[5][256];
    __shared__ float s_alpha[5];

    const float* qrow  = g_q  + (size_t)bs * H_SZ;
    const float* werow = g_we + (size_t)bs * W_SZ * H_SZ;
    const float* lorow = lo   + (size_t)bs * H_SZ;

    float qv[3], lov[3], wev[5][3];
    #pragma unroll
    for (int e = 0; e < 3; e++) {
        int h = tid + e * 256;
        qv[e]  = qrow[h];
        lov[e] = lorow[h];
        #pragma unroll
        for (int w = 0; w < W_SZ; w++)
            wev[w][e] = werow[w * H_SZ + h];
    }

    #pragma unroll
    for (int w = 0; w < W_SZ; w++) {
        float d = 0.f;
        #pragma unroll
        for (int e = 0; e < 3; e++)
            d = fmaf(qv[e], wev[w][e], d);
        red[w][tid] = d;
    }
    __syncthreads();
    for (int s = 128; s > 0; s >>= 1) {
        if (tid < s) {
            #pragma unroll
            for (int w = 0; w < W_SZ; w++)
                red[w][tid] += red[w][tid + s];
        }
        __syncthreads();
    }

    if (tid == 0) {
        float sc[5];
        float mx = -1e30f;
        #pragma unroll
        for (int w = 0; w < W_SZ; w++) {
            float mk = g_maskf[(size_t)bs * W_SZ + w];
            sc[w] = red[w][0] + (1.f - mk) * (-10000.f);
            mx = fmaxf(mx, sc[w]);
        }
        float sum = 0.f;
        #pragma unroll
        for (int w = 0; w < W_SZ; w++) {
            sc[w] = expf(sc[w] - mx);
            sum += sc[w];
        }
        float inv = 1.f / sum;
        #pragma unroll
        for (int w = 0; w < W_SZ; w++)
            s_alpha[w] = sc[w] * inv;
    }
    __syncthreads();

    float alpha[5];
    #pragma unroll
    for (int w = 0; w < W_SZ; w++) alpha[w] = s_alpha[w];

    float hv[3];
    float psum = 0.f, psq = 0.f;
    #pragma unroll
    for (int e = 0; e < 3; e++) {
        float agg = 0.f;
        #pragma unroll
        for (int w = 0; w < W_SZ; w++)
            agg = fmaf(alpha[w], wev[w][e], agg);
        hv[e] = lov[e] + agg;
        psum += hv[e];
        psq  = fmaf(hv[e], hv[e], psq);
    }
    __syncthreads();
    red[0][tid] = psum;
    red[1][tid] = psq;
    __syncthreads();
    for (int s = 128; s > 0; s >>= 1) {
        if (tid < s) {
            red[0][tid] += red[0][tid + s];
            red[1][tid] += red[1][tid + s];
        }
        __syncthreads();
    }

    const float inv_h = 1.f / (float)H_SZ;
    float mu   = red[0][0] * inv_h;
    float var  = red[1][0] * inv_h - mu * mu;
    float rstd = rsqrtf(var + 1e-12f);

    #pragma unroll
    for (int e = 0; e < 3; e++) {
        int h = tid + e * 256;
        out[(size_t)bs * H_SZ + h] = (hv[e] - mu) * rstd * gamma[h] + beta[h];
    }
}

// ---------------------------------------------------------------------------
// Launch
// ---------------------------------------------------------------------------
extern "C" void kernel_launch(void* const* d_in, const int* in_sizes, int n_in,
                              void* d_out, int out_size)
{
    const float* lo     = (const float*)d_in[0];
    const float* we_in  = (const float*)d_in[1];
    const void*  mask   = d_in[2];
    const float* W1     = (const float*)d_in[3];
    const float* b1     = (const float*)d_in[4];
    const float* W2     = (const float*)d_in[5];
    const float* b2     = (const float*)d_in[6];
    const float* attn_W = (const float*)d_in[7];
    const float* gamma  = (const float*)d_in[8];
    const float* beta   = (const float*)d_in[9];
    float*       out    = (float*)d_out;

    float *tmp_p, *we_p, *q_p;
    cudaGetSymbolAddress((void**)&tmp_p, g_tmp);
    cudaGetSymbolAddress((void**)&we_p,  g_we);
    cudaGetSymbolAddress((void**)&q_p,   g_q);

    // Allow >48KB dynamic smem for the GEMM instantiations
    cudaFuncSetAttribute(tf32_gemm<true,  true >, cudaFuncAttributeMaxDynamicSharedMemorySize, SMEM_BYTES);
    cudaFuncSetAttribute(tf32_gemm<false, true >, cudaFuncAttributeMaxDynamicSharedMemorySize, SMEM_BYTES);
    cudaFuncSetAttribute(tf32_gemm<false, false>, cudaFuncAttributeMaxDynamicSharedMemorySize, SMEM_BYTES);

    // Mask dtype detection + normalization
    int* flag_p;
    cudaGetSymbolAddress((void**)&flag_p, g_mask_is32);
    cudaMemsetAsync(flag_p, 0, sizeof(int));
    detect_mask_kernel<<<(NMASK / 2 + 255) / 256, 256>>>((const long long*)mask);
    normalize_mask_kernel<<<(NMASK + 255) / 256, 256>>>(mask);

    dim3 blk(256);
    dim3 grid1(H_SZ / 128, M1 / 128);   // (6, 320)
    dim3 grid3(H_SZ / 128, MQ / 128);   // (6, 64)

    // GEMM1: tmp = tanh(WE @ W1 + b1)   [40960 x 768], K=200
    tf32_gemm<true,  true ><<<grid1, blk, SMEM_BYTES>>>(we_in, W1, b1, tmp_p, M1, H_SZ, D_SZ);
    // GEMM2: we = tmp @ W2 + b2         [40960 x 768], K=768
    tf32_gemm<false, true ><<<grid1, blk, SMEM_BYTES>>>(tmp_p, W2, b2, we_p, M1, H_SZ, H_SZ);
    // GEMM3: q = layer_output @ attn_W  [8192 x 768], K=768
    tf32_gemm<false, false><<<grid3, blk, SMEM_BYTES>>>(lo, attn_W, nullptr, q_p, MQ, H_SZ, H_SZ);
    // Fused attention + residual + LayerNorm
    epilogue_kernel<<<MQ, 256>>>(lo, gamma, beta, out);
}

// round 4
// speedup vs baseline: 3.4249x; 1.4063x over previous
#include <cuda_runtime.h>
#include <math.h>
#include <stdint.h>

// Problem dimensions (fixed by the reference)
#define B_SZ 16
#define S_SZ 512
#define W_SZ 5
#define D_SZ 200
#define H_SZ 768
#define M1 (B_SZ * S_SZ * W_SZ)   // 40960
#define MQ (B_SZ * S_SZ)          // 8192
#define NMASK (MQ * W_SZ)         // 40960

// Scratch (alloc-free rule: __device__ globals)
__device__ float g_tmp[M1 * H_SZ];     // tanh(WE @ W1 + b1), stored tf32-rounded
__device__ float g_we [M1 * H_SZ];     // word_transform output (fp32)
__device__ float g_q  [MQ * H_SZ];     // layer_output @ attn_W (fp32)
__device__ float g_maskf[NMASK];
__device__ int   g_mask_is32;
// tf32-pre-rounded weights
__device__ float g_W1R[D_SZ * H_SZ];
__device__ float g_W2R[H_SZ * H_SZ];
__device__ float g_aWR[H_SZ * H_SZ];

__device__ __forceinline__ uint32_t f2tf32(float f)
{
    uint32_t u;
    asm("cvt.rna.tf32.f32 %0, %1;\n" : "=r"(u) : "f"(f));
    return u;
}

// ---------------------------------------------------------------------------
// Pre-round weights to tf32 bit patterns (stored as float)
// ---------------------------------------------------------------------------
__global__ void round_tf32_kernel(const float* __restrict__ in,
                                  float* __restrict__ out, int n)
{
    int i = blockIdx.x * blockDim.x + threadIdx.x;
    if (i < n) out[i] = __uint_as_float(f2tf32(in[i]));
}

// ---------------------------------------------------------------------------
// Mask dtype detection + normalization (proven in R2/R3)
// ---------------------------------------------------------------------------
__global__ void detect_mask_kernel(const long long* __restrict__ m64)
{
    int i = blockIdx.x * blockDim.x + threadIdx.x;
    if (i < NMASK / 2) {
        unsigned long long v = (unsigned long long)m64[i];
        if (v > 1ULL) atomicOr(&g_mask_is32, 1);
    }
}
__global__ void normalize_mask_kernel(const void* __restrict__ mraw)
{
    int i = blockIdx.x * blockDim.x + threadIdx.x;
    if (i >= NMASK) return;
    float v;
    if (g_mask_is32) v = (float)((const int*)mraw)[i];
    else             v = (float)((const long long*)mraw)[i];
    g_maskf[i] = v;
}

// ---------------------------------------------------------------------------
// TF32 tensor-core GEMM: C[M,N] = op(A[M,K] @ B[K,N] + bias)
// BM=128, BN=128, BK=32, 128 threads = 4 warps (2x2), warp tile 64x64.
// B is always pre-rounded tf32 bits; A rounded in-loop iff CVT_A.
// If ROUND_OUT, epilogue stores tf32-rounded output (feeds next GEMM's A).
// ---------------------------------------------------------------------------
#define AS_STRIDE 36
#define BS_STRIDE 136
#define AS_ELEMS (128 * AS_STRIDE)
#define BS_ELEMS (32 * BS_STRIDE)
#define SMEM_BYTES ((2 * AS_ELEMS + 2 * BS_ELEMS) * 4)   // 71680

__device__ __forceinline__ void cp_async16(uint32_t dst, const void* src, int ssize)
{
    asm volatile("cp.async.cg.shared.global [%0], [%1], 16, %2;\n"
                 :: "r"(dst), "l"(src), "r"(ssize));
}
__device__ __forceinline__ void cp_commit() { asm volatile("cp.async.commit_group;\n"); }
__device__ __forceinline__ void cp_wait0()  { asm volatile("cp.async.wait_group 0;\n"); }

template <bool TANH, bool BIAS, bool CVT_A, bool ROUND_OUT>
__global__ __launch_bounds__(128, 2)
void tf32_gemm(const float* __restrict__ A,
               const float* __restrict__ Bm,
               const float* __restrict__ bias,
               float* __restrict__ C,
               int M, int N, int K)
{
    extern __shared__ float smem[];
    float* As[2] = { smem,                smem + AS_ELEMS };
    float* Bs[2] = { smem + 2 * AS_ELEMS, smem + 2 * AS_ELEMS + BS_ELEMS };

    const int tid  = threadIdx.x;       // 0..127
    const int lane = tid & 31;
    const int wid  = tid >> 5;          // 0..3
    const int wm   = (wid & 1) * 64;
    const int wn   = (wid >> 1) * 64;
    const int g    = lane >> 2;         // 0..7
    const int tg   = lane & 3;          // 0..3
    const int m0   = blockIdx.y * 128;
    const int n0   = blockIdx.x * 128;

    // cp.async coords: A tile 128x32 = 1024 float4, 8/thread
    int ar[8], br[8];
    #pragma unroll
    for (int i = 0; i < 8; i++) {
        ar[i] = (tid + i * 128) >> 3;
        br[i] = (tid + i * 128) >> 5;
    }
    const int ac = (tid & 7) * 4;
    const int bc = (tid & 31) * 4;

    uint32_t as_base[2], bs_base[2];
    as_base[0] = (uint32_t)__cvta_generic_to_shared(As[0]);
    as_base[1] = (uint32_t)__cvta_generic_to_shared(As[1]);
    bs_base[0] = (uint32_t)__cvta_generic_to_shared(Bs[0]);
    bs_base[1] = (uint32_t)__cvta_generic_to_shared(Bs[1]);

    float acc[4][8][4];
    #pragma unroll
    for (int mi = 0; mi < 4; mi++)
        #pragma unroll
        for (int ni = 0; ni < 8; ni++)
            #pragma unroll
            for (int r = 0; r < 4; r++)
                acc[mi][ni][r] = 0.f;

    const int tiles = (K + 31) / 32;

    auto load_tile = [&](int buf, int k0) {
        #pragma unroll
        for (int i = 0; i < 8; i++) {
            int gk = k0 + ac;
            int ok = (gk < K) ? 16 : 0;
            int gks = ok ? gk : 0;
            cp_async16(as_base[buf] + (ar[i] * AS_STRIDE + ac) * 4,
                       A + (size_t)(m0 + ar[i]) * K + gks, ok);
        }
        #pragma unroll
        for (int i = 0; i < 8; i++) {
            int gk = k0 + br[i];
            int ok = (gk < K) ? 16 : 0;
            int gks = ok ? gk : 0;
            cp_async16(bs_base[buf] + (br[i] * BS_STRIDE + bc) * 4,
                       Bm + (size_t)gks * N + n0 + bc, ok);
        }
        cp_commit();
    };

    load_tile(0, 0);

    int buf = 0;
    for (int t = 0; t < tiles; t++) {
        cp_wait0();
        __syncthreads();
        if (t + 1 < tiles)
            load_tile(buf ^ 1, (t + 1) * 32);

        const uint32_t* Ab = reinterpret_cast<const uint32_t*>(As[buf]);
        const uint32_t* Bb = reinterpret_cast<const uint32_t*>(Bs[buf]);

        #pragma unroll
        for (int s = 0; s < 4; s++) {
            const int kb = s * 8;
            uint32_t af[4][4];
            #pragma unroll
            for (int mi = 0; mi < 4; mi++) {
                const uint32_t* p = Ab + (wm + mi * 16 + g) * AS_STRIDE + kb + tg;
                uint32_t a0 = p[0];
                uint32_t a1 = p[8 * AS_STRIDE];
                uint32_t a2 = p[4];
                uint32_t a3 = p[8 * AS_STRIDE + 4];
                if (CVT_A) {
                    a0 = f2tf32(__uint_as_float(a0));
                    a1 = f2tf32(__uint_as_float(a1));
                    a2 = f2tf32(__uint_as_float(a2));
                    a3 = f2tf32(__uint_as_float(a3));
                }
                af[mi][0] = a0; af[mi][1] = a1; af[mi][2] = a2; af[mi][3] = a3;
            }
            uint32_t bf[8][2];
            #pragma unroll
            for (int ni = 0; ni < 8; ni++) {
                const uint32_t* p = Bb + (kb + tg) * BS_STRIDE + wn + ni * 8 + g;
                bf[ni][0] = p[0];
                bf[ni][1] = p[4 * BS_STRIDE];
            }
            #pragma unroll
            for (int mi = 0; mi < 4; mi++)
                #pragma unroll
                for (int ni = 0; ni < 8; ni++) {
                    asm volatile(
                        "mma.sync.aligned.m16n8k8.row.col.f32.tf32.tf32.f32 "
                        "{%0,%1,%2,%3}, {%4,%5,%6,%7}, {%8,%9}, {%0,%1,%2,%3};\n"
                        : "+f"(acc[mi][ni][0]), "+f"(acc[mi][ni][1]),
                          "+f"(acc[mi][ni][2]), "+f"(acc[mi][ni][3])
                        : "r"(af[mi][0]), "r"(af[mi][1]), "r"(af[mi][2]), "r"(af[mi][3]),
                          "r"(bf[ni][0]), "r"(bf[ni][1]));
                }
        }
        __syncthreads();
        buf ^= 1;
    }

    // epilogue
    #pragma unroll
    for (int ni = 0; ni < 8; ni++) {
        const int col = n0 + wn + ni * 8 + tg * 2;
        float b0 = 0.f, b1 = 0.f;
        if (BIAS) { b0 = bias[col]; b1 = bias[col + 1]; }
        #pragma unroll
        for (int mi = 0; mi < 4; mi++) {
            const int row = m0 + wm + mi * 16 + g;
            float r0 = acc[mi][ni][0] + b0;
            float r1 = acc[mi][ni][1] + b1;
            float r2 = acc[mi][ni][2] + b0;
            float r3 = acc[mi][ni][3] + b1;
            if (TANH) { r0 = tanhf(r0); r1 = tanhf(r1); r2 = tanhf(r2); r3 = tanhf(r3); }
            if (ROUND_OUT) {
                r0 = __uint_as_float(f2tf32(r0));
                r1 = __uint_as_float(f2tf32(r1));
                r2 = __uint_as_float(f2tf32(r2));
                r3 = __uint_as_float(f2tf32(r3));
            }
            *reinterpret_cast<float2*>(&C[(size_t)row * N + col])       = make_float2(r0, r1);
            *reinterpret_cast<float2*>(&C[(size_t)(row + 8) * N + col]) = make_float2(r2, r3);
        }
    }
}

// ---------------------------------------------------------------------------
// Fused epilogue (unchanged from passing R2/R3 version)
// ---------------------------------------------------------------------------
__global__ __launch_bounds__(256)
void epilogue_kernel(const float* __restrict__ lo,
                     const float* __restrict__ gamma,
                     const float* __restrict__ beta,
                     float* __restrict__ out)
{
    const int bs  = blockIdx.x;
    const int tid = threadIdx.x;

    __shared__ float red[5][256];
    __shared__ float s_alpha[5];

    const float* qrow  = g_q  + (size_t)bs * H_SZ;
    const float* werow = g_we + (size_t)bs * W_SZ * H_SZ;
    const float* lorow = lo   + (size_t)bs * H_SZ;

    float qv[3], lov[3], wev[5][3];
    #pragma unroll
    for (int e = 0; e < 3; e++) {
        int h = tid + e * 256;
        qv[e]  = qrow[h];
        lov[e] = lorow[h];
        #pragma unroll
        for (int w = 0; w < W_SZ; w++)
            wev[w][e] = werow[w * H_SZ + h];
    }

    #pragma unroll
    for (int w = 0; w < W_SZ; w++) {
        float d = 0.f;
        #pragma unroll
        for (int e = 0; e < 3; e++)
            d = fmaf(qv[e], wev[w][e], d);
        red[w][tid] = d;
    }
    __syncthreads();
    for (int s = 128; s > 0; s >>= 1) {
        if (tid < s) {
            #pragma unroll
            for (int w = 0; w < W_SZ; w++)
                red[w][tid] += red[w][tid + s];
        }
        __syncthreads();
    }

    if (tid == 0) {
        float sc[5];
        float mx = -1e30f;
        #pragma unroll
        for (int w = 0; w < W_SZ; w++) {
            float mk = g_maskf[(size_t)bs * W_SZ + w];
            sc[w] = red[w][0] + (1.f - mk) * (-10000.f);
            mx = fmaxf(mx, sc[w]);
        }
        float sum = 0.f;
        #pragma unroll
        for (int w = 0; w < W_SZ; w++) {
            sc[w] = expf(sc[w] - mx);
            sum += sc[w];
        }
        float inv = 1.f / sum;
        #pragma unroll
        for (int w = 0; w < W_SZ; w++)
            s_alpha[w] = sc[w] * inv;
    }
    __syncthreads();

    float alpha[5];
    #pragma unroll
    for (int w = 0; w < W_SZ; w++) alpha[w] = s_alpha[w];

    float hv[3];
    float psum = 0.f, psq = 0.f;
    #pragma unroll
    for (int e = 0; e < 3; e++) {
        float agg = 0.f;
        #pragma unroll
        for (int w = 0; w < W_SZ; w++)
            agg = fmaf(alpha[w], wev[w][e], agg);
        hv[e] = lov[e] + agg;
        psum += hv[e];
        psq  = fmaf(hv[e], hv[e], psq);
    }
    __syncthreads();
    red[0][tid] = psum;
    red[1][tid] = psq;
    __syncthreads();
    for (int s = 128; s > 0; s >>= 1) {
        if (tid < s) {
            red[0][tid] += red[0][tid + s];
            red[1][tid] += red[1][tid + s];
        }
        __syncthreads();
    }

    const float inv_h = 1.f / (float)H_SZ;
    float mu   = red[0][0] * inv_h;
    float var  = red[1][0] * inv_h - mu * mu;
    float rstd = rsqrtf(var + 1e-12f);

    #pragma unroll
    for (int e = 0; e < 3; e++) {
        int h = tid + e * 256;
        out[(size_t)bs * H_SZ + h] = (hv[e] - mu) * rstd * gamma[h] + beta[h];
    }
}

// ---------------------------------------------------------------------------
// Launch
// ---------------------------------------------------------------------------
extern "C" void kernel_launch(void* const* d_in, const int* in_sizes, int n_in,
                              void* d_out, int out_size)
{
    const float* lo     = (const float*)d_in[0];
    const float* we_in  = (const float*)d_in[1];
    const void*  mask   = d_in[2];
    const float* W1     = (const float*)d_in[3];
    const float* b1     = (const float*)d_in[4];
    const float* W2     = (const float*)d_in[5];
    const float* b2     = (const float*)d_in[6];
    const float* attn_W = (const float*)d_in[7];
    const float* gamma  = (const float*)d_in[8];
    const float* beta   = (const float*)d_in[9];
    float*       out    = (float*)d_out;

    float *tmp_p, *we_p, *q_p, *w1r_p, *w2r_p, *awr_p;
    cudaGetSymbolAddress((void**)&tmp_p, g_tmp);
    cudaGetSymbolAddress((void**)&we_p,  g_we);
    cudaGetSymbolAddress((void**)&q_p,   g_q);
    cudaGetSymbolAddress((void**)&w1r_p, g_W1R);
    cudaGetSymbolAddress((void**)&w2r_p, g_W2R);
    cudaGetSymbolAddress((void**)&awr_p, g_aWR);

    cudaFuncSetAttribute(tf32_gemm<true,  true,  true,  true >, cudaFuncAttributeMaxDynamicSharedMemorySize, SMEM_BYTES);
    cudaFuncSetAttribute(tf32_gemm<false, true,  false, false>, cudaFuncAttributeMaxDynamicSharedMemorySize, SMEM_BYTES);
    cudaFuncSetAttribute(tf32_gemm<false, false, true,  false>, cudaFuncAttributeMaxDynamicSharedMemorySize, SMEM_BYTES);

    // Mask handling
    int* flag_p;
    cudaGetSymbolAddress((void**)&flag_p, g_mask_is32);
    cudaMemsetAsync(flag_p, 0, sizeof(int));
    detect_mask_kernel<<<(NMASK / 2 + 255) / 256, 256>>>((const long long*)mask);
    normalize_mask_kernel<<<(NMASK + 255) / 256, 256>>>(mask);

    // Pre-round weights to tf32
    round_tf32_kernel<<<(D_SZ * H_SZ + 255) / 256, 256>>>(W1, w1r_p, D_SZ * H_SZ);
    round_tf32_kernel<<<(H_SZ * H_SZ + 255) / 256, 256>>>(W2, w2r_p, H_SZ * H_SZ);
    round_tf32_kernel<<<(H_SZ * H_SZ + 255) / 256, 256>>>(attn_W, awr_p, H_SZ * H_SZ);

    dim3 blk(128);
    dim3 grid1(H_SZ / 128, M1 / 128);   // (6, 320)
    dim3 grid3(H_SZ / 128, MQ / 128);   // (6, 64)

    // GEMM1: tmp = round(tanh(WE @ W1 + b1))   [40960 x 768], K=200 (A cvt in-loop)
    tf32_gemm<true,  true,  true,  true ><<<grid1, blk, SMEM_BYTES>>>(we_in, w1r_p, b1, tmp_p, M1, H_SZ, D_SZ);
    // GEMM2: we = tmp @ W2 + b2                [40960 x 768], K=768 (no cvt at all)
    tf32_gemm<false, true,  false, false><<<grid1, blk, SMEM_BYTES>>>(tmp_p, w2r_p, b2, we_p, M1, H_SZ, H_SZ);
    // GEMM3: q = lo @ attn_W                   [8192 x 768], K=768 (A cvt in-loop)
    tf32_gemm<false, false, true,  false><<<grid3, blk, SMEM_BYTES>>>(lo, awr_p, nullptr, q_p, MQ, H_SZ, H_SZ);
    // Fused attention + residual + LayerNorm
    epilogue_kernel<<<MQ, 256>>>(lo, gamma, beta, out);
}